// round 12
// baseline (speedup 1.0000x reference)
#include <cuda_runtime.h>
#include <cuda_bf16.h>
#include <cstdint>

#define NN  50000
#define NC  256
#define DD  64
#define HH  128
#define EVV 800000
#define EVC 400000

#define CAPVV 64
#define CAPVC 32

#define VTILES 391                 // ceil(50000/128)
#define CTILES 2
#define FUSED_GRID (VTILES + CTILES)   // 393

// ---- smem weight image (bytes). Row strides: stride/4 mod 32 == 4 ----
#define W1_STRIDE_W 36
#define W2_STRIDE_W 68
#define SM_W1H 0                   // 128 rows * 144B = 18432
#define SM_W1L 18432
#define SM_W2H 36864               // 64 rows * 272B = 17408
#define SM_W2L 54272
#define SM_B1S 71680
#define SM_B2S 72192
#define WBLOB  72448               // total smem per block

typedef unsigned long long ull;

// ---------------- scratch (device globals; zero-initialized) ----------------
__device__ float g_yv[NN * DD];
__device__ float g_yc[NC * DD];
__device__ int   d_cnt_vv[NN];
__device__ int   d_cnt_vc[NN];
__device__ int   d_slot_vv[NN * CAPVV];   // pre-scaled src offsets (src<<4)
__device__ int   d_slot_vc[NN * CAPVC];
__device__ int   d_flag;                  // weight-blob ready flag
__device__ __align__(16) unsigned char g_wblob[2][WBLOB];

// ---------------- helpers ----------------------------------------------------
__device__ __forceinline__ void bsplit(float v, unsigned short& h, unsigned short& l) {
    __nv_bfloat16 bh = __float2bfloat16(v);
    float r = v - __bfloat162float(bh);
    __nv_bfloat16 bl = __float2bfloat16(r);
    h = __bfloat16_as_ushort(bh);
    l = __bfloat16_as_ushort(bl);
}
__device__ __forceinline__ uint32_t pkbf(float hi_val, float lo_val) {
    uint32_t r;
    asm("cvt.rn.bf16x2.f32 %0, %1, %2;" : "=r"(r) : "f"(hi_val), "f"(lo_val));
    return r;
}
// split a float2 into packed bf16x2 hi word + residual lo word
__device__ __forceinline__ void split2(float2 v, uint32_t& wh, uint32_t& wl) {
    wh = pkbf(v.y, v.x);
    const float r0 = v.x - __uint_as_float(wh << 16);
    const float r1 = v.y - __uint_as_float(wh & 0xFFFF0000u);
    wl = pkbf(r1, r0);
}
__device__ __forceinline__ void mma16816(float* c, const uint32_t* a,
                                         uint32_t b0, uint32_t b1) {
    asm volatile(
        "mma.sync.aligned.m16n8k16.row.col.f32.bf16.bf16.f32 "
        "{%0,%1,%2,%3}, {%4,%5,%6,%7}, {%8,%9}, {%0,%1,%2,%3};"
        : "+f"(c[0]), "+f"(c[1]), "+f"(c[2]), "+f"(c[3])
        : "r"(a[0]), "r"(a[1]), "r"(a[2]), "r"(a[3]), "r"(b0), "r"(b1));
}
__device__ __forceinline__ ull pk2(float lo, float hi) {
    ull r; asm("mov.b64 %0, {%1, %2};" : "=l"(r) : "f"(lo), "f"(hi)); return r;
}
__device__ __forceinline__ void upk2(ull v, float& lo, float& hi) {
    asm("mov.b64 {%0, %1}, %2;" : "=f"(lo), "=f"(hi) : "l"(v));
}
__device__ __forceinline__ ull fadd2(ull a, ull b) {
    ull d; asm("add.rn.f32x2 %0, %1, %2;" : "=l"(d) : "l"(a), "l"(b)); return d;
}

// ---------------------------------------------------------------------------
__device__ __forceinline__ void fill_slice(
    int bid, int t,
    const int* __restrict__ src_vv, const int* __restrict__ dst_vv,
    const int* __restrict__ src_vc, const int* __restrict__ dst_vc)
{
    const int g = bid * 256 + t;
    const int stride = FUSED_GRID * 256;
    for (int i = g; i < EVV; i += stride) {
        const int d = dst_vv[i];
        const int p = atomicAdd(&d_cnt_vv[d], 1);
        if (p < CAPVV) d_slot_vv[d * CAPVV + p] = src_vv[i] << 4;
    }
    for (int i = g; i < EVC; i += stride) {
        const int d = dst_vc[i];
        const int p = atomicAdd(&d_cnt_vc[d], 1);
        if (p < CAPVC) d_slot_vc[d * CAPVC + p] = src_vc[i] << 4;
    }
}

__device__ __forceinline__ void prep_weights(
    int t,
    const float* __restrict__ W1v, const float* __restrict__ b1v,
    const float* __restrict__ W2v, const float* __restrict__ b2v,
    const float* __restrict__ W1c, const float* __restrict__ b1c,
    const float* __restrict__ W2c, const float* __restrict__ b2c)
{
#pragma unroll
    for (int net = 0; net < 2; net++) {
        const float* W1 = net ? W1c : W1v;
        const float* W2 = net ? W2c : W2v;
        unsigned char* blob = g_wblob[net];
        unsigned short* W1h = (unsigned short*)(blob + SM_W1H);
        unsigned short* W1l = (unsigned short*)(blob + SM_W1L);
        unsigned short* W2h = (unsigned short*)(blob + SM_W2H);
        unsigned short* W2l = (unsigned short*)(blob + SM_W2L);
        // W1 [64 k][128 n] -> image [n][k]
        for (int idx = t; idx < HH * DD; idx += 256) {
            const int n = idx >> 6;
            const int k = idx & 63;
            unsigned short h, l;
            bsplit(W1[k * HH + n], h, l);
            W1h[n * (2 * W1_STRIDE_W) + k] = h;
            W1l[n * (2 * W1_STRIDE_W) + k] = l;
        }
        // W2 [128 j][64 c] -> image [c][j]
        for (int idx = t; idx < DD * HH; idx += 256) {
            const int c = idx >> 7;
            const int j = idx & 127;
            unsigned short h, l;
            bsplit(W2[j * DD + c], h, l);
            W2h[c * (2 * W2_STRIDE_W) + j] = h;
            W2l[c * (2 * W2_STRIDE_W) + j] = l;
        }
        const float* B1 = net ? b1c : b1v;
        const float* B2 = net ? b2c : b2v;
        if (t < HH) ((float*)(blob + SM_B1S))[t] = B1[t];
        if (t < DD) ((float*)(blob + SM_B2S))[t] = B2[t];
    }
}

// ---------------------------------------------------------------------------
// Fused: block 0 builds the weight blob (others fill meanwhile), then every
// block runs one 128-row HMMA MLP tile; block 0 does its fill slice last.
// A-fragments are built in registers straight from global x (no X smem).
// ---------------------------------------------------------------------------
__global__ void __launch_bounds__(256, 2) fused_kernel(
    const float* __restrict__ x_v, const float* __restrict__ x_c,
    const float* __restrict__ W1v, const float* __restrict__ b1v,
    const float* __restrict__ W2v, const float* __restrict__ b2v,
    const float* __restrict__ W1c, const float* __restrict__ b1c,
    const float* __restrict__ W2c, const float* __restrict__ b2c,
    const int* __restrict__ src_vv, const int* __restrict__ dst_vv,
    const int* __restrict__ src_vc, const int* __restrict__ dst_vc)
{
    const int t = threadIdx.x;
    const int bid = blockIdx.x;

    if (bid == 0) {
        prep_weights(t, W1v, b1v, W2v, b2v, W1c, b1c, W2c, b2c);
        __threadfence();
        __syncthreads();
        if (t == 0) atomicExch(&d_flag, 1);
    } else {
        fill_slice(bid, t, src_vv, dst_vv, src_vc, dst_vc);
        if (t == 0) {
            while (atomicAdd(&d_flag, 0) == 0) {}
            __threadfence();
        }
        __syncthreads();
    }

    // ---------------- MLP tile ----------------
    extern __shared__ char smem[];
    const int tile = bid;
    const bool is_color = (tile < CTILES);
    const float* X  = is_color ? x_c : x_v;
    float*       Y  = is_color ? g_yc : g_yv;
    const int row0 = is_color ? tile * 128 : (tile - CTILES) * 128;
    const int nrows = is_color ? NC : NN;
    const int rem = min(128, nrows - row0);

    const int warp = t >> 5;
    const int lane = t & 31;
    const int qr = lane >> 2;
    const int qc = lane & 3;

    // coalesced copy of the pre-built weight image (L2)
    {
        const float4* src = (const float4*)g_wblob[is_color ? 1 : 0];
        float4* dst = (float4*)smem;
        for (int idx = t; idx < WBLOB / 16; idx += 256)
            dst[idx] = __ldcg(src + idx);
    }

    // A-fragments straight from global x, split in registers
    uint32_t ah[4][4], al[4][4];
    {
        const float* Xb = X + (size_t)row0 * DD;
        const int r0 = warp * 16 + qr;
        const bool ok0 = (r0 < rem), ok1 = (r0 + 8 < rem);
        const float2 z = make_float2(0.f, 0.f);
#pragma unroll
        for (int kb = 0; kb < 4; kb++) {
            const int k = kb * 16 + 2 * qc;
            float2 v00 = ok0 ? *(const float2*)(Xb + (size_t)r0 * DD + k) : z;
            float2 v10 = ok1 ? *(const float2*)(Xb + (size_t)(r0 + 8) * DD + k) : z;
            float2 v01 = ok0 ? *(const float2*)(Xb + (size_t)r0 * DD + k + 8) : z;
            float2 v11 = ok1 ? *(const float2*)(Xb + (size_t)(r0 + 8) * DD + k + 8) : z;
            split2(v00, ah[kb][0], al[kb][0]);
            split2(v10, ah[kb][1], al[kb][1]);
            split2(v01, ah[kb][2], al[kb][2]);
            split2(v11, ah[kb][3], al[kb][3]);
        }
    }
    __syncthreads();

    const uint32_t* W1h32 = (const uint32_t*)(smem + SM_W1H);
    const uint32_t* W1l32 = (const uint32_t*)(smem + SM_W1L);
    const uint32_t* W2h32 = (const uint32_t*)(smem + SM_W2H);
    const uint32_t* W2l32 = (const uint32_t*)(smem + SM_W2L);
    const float* b1s = (const float*)(smem + SM_B1S);
    const float* b2s = (const float*)(smem + SM_B2S);

    // ---- layer 1 + epilogue, in two nt-halves (register pressure cap) ----
    uint32_t a2h[16][2], a2l[16][2];
#pragma unroll
    for (int half = 0; half < 2; half++) {
        float acc[8][4];
#pragma unroll
        for (int nt = 0; nt < 8; nt++)
#pragma unroll
            for (int i = 0; i < 4; i++) acc[nt][i] = 0.0f;
#pragma unroll
        for (int kb = 0; kb < 4; kb++) {
#pragma unroll
            for (int nt2 = 0; nt2 < 8; nt2++) {
                const int nt = half * 8 + nt2;
                const int bw = (nt * 8 + qr) * W1_STRIDE_W + kb * 8 + qc;
                const uint32_t bh0 = W1h32[bw], bh1 = W1h32[bw + 4];
                const uint32_t bl0 = W1l32[bw], bl1 = W1l32[bw + 4];
                mma16816(acc[nt2], ah[kb], bh0, bh1);
                mma16816(acc[nt2], ah[kb], bl0, bl1);
                mma16816(acc[nt2], al[kb], bh0, bh1);
            }
        }
#pragma unroll
        for (int nt2 = 0; nt2 < 8; nt2++) {
            const int nt = half * 8 + nt2;
            const int cn = nt * 8 + 2 * qc;
            const float2 bb = *(const float2*)(b1s + cn);
            float2 p0, p1;
            p0.x = fmaxf(acc[nt2][0] + bb.x, 0.0f);
            p0.y = fmaxf(acc[nt2][1] + bb.y, 0.0f);
            p1.x = fmaxf(acc[nt2][2] + bb.x, 0.0f);
            p1.y = fmaxf(acc[nt2][3] + bb.y, 0.0f);
            split2(p0, a2h[nt][0], a2l[nt][0]);
            split2(p1, a2h[nt][1], a2l[nt][1]);
        }
    }

    // ---- layer 2: acc2[8][4] = H(128x128) @ W2(128x64) ----
    float acc2[8][4];
#pragma unroll
    for (int nt = 0; nt < 8; nt++)
#pragma unroll
        for (int i = 0; i < 4; i++) acc2[nt][i] = 0.0f;

#pragma unroll
    for (int kb = 0; kb < 8; kb++) {
        uint32_t fh[4], fl[4];
        fh[0] = a2h[2 * kb][0];     fh[1] = a2h[2 * kb][1];
        fh[2] = a2h[2 * kb + 1][0]; fh[3] = a2h[2 * kb + 1][1];
        fl[0] = a2l[2 * kb][0];     fl[1] = a2l[2 * kb][1];
        fl[2] = a2l[2 * kb + 1][0]; fl[3] = a2l[2 * kb + 1][1];
#pragma unroll
        for (int nt = 0; nt < 8; nt++) {
            const int bw = (nt * 8 + qr) * W2_STRIDE_W + kb * 8 + qc;
            const uint32_t bh0 = W2h32[bw], bh1 = W2h32[bw + 4];
            const uint32_t bl0 = W2l32[bw], bl1 = W2l32[bw + 4];
            mma16816(acc2[nt], fh, bh0, bh1);
            mma16816(acc2[nt], fh, bl0, bl1);
            mma16816(acc2[nt], fl, bh0, bh1);
        }
    }

    // ---- epilogue 2: y = acc2 + b2 -> global ----
    {
        const int rl0 = warp * 16 + qr;
#pragma unroll
        for (int nt = 0; nt < 8; nt++) {
            const int c = nt * 8 + 2 * qc;
            const float2 bb = *(const float2*)(b2s + c);
            if (rl0 < rem) {
                float2 y; y.x = acc2[nt][0] + bb.x; y.y = acc2[nt][1] + bb.y;
                *(float2*)(Y + (size_t)(row0 + rl0) * DD + c) = y;
            }
            if (rl0 + 8 < rem) {
                float2 y; y.x = acc2[nt][2] + bb.x; y.y = acc2[nt][3] + bb.y;
                *(float2*)(Y + (size_t)(row0 + rl0 + 8) * DD + c) = y;
            }
        }
    }

    if (bid == 0) fill_slice(0, t, src_vv, dst_vv, src_vc, dst_vc);
}

// ---------------------------------------------------------------------------
// Gather: 2 vertices per warp, lane = float4 chunk; pre-scaled int4 slots.
// ---------------------------------------------------------------------------
__global__ void __launch_bounds__(256) gather_kernel(
    const float* __restrict__ x_v, float* __restrict__ out)
{
    const int gwarp = (blockIdx.x * 256 + threadIdx.x) >> 5;
    const int lane = threadIdx.x & 31;
    const int half = lane >> 4;
    const int q = lane & 15;
    const int v = gwarp * 2 + half;

    float4 a4 = ((const float4*)x_v)[v * 16 + q];
    ull acc_lo = pk2(a4.x, a4.y);
    ull acc_hi = pk2(a4.z, a4.w);

    // vertex->vertex in-edges (y_v L2-resident)
    {
        const int cnt = min(d_cnt_vv[v], CAPVV);
        const int* slots = d_slot_vv + v * CAPVV;
        const int4* slots4 = (const int4*)slots;
        const ulonglong2* yv = (const ulonglong2*)g_yv;
        int i = 0;
        for (; i + 8 <= cnt; i += 8) {
            const int4 sa = slots4[i >> 2];
            const int4 sb = slots4[(i >> 2) + 1];
            ulonglong2 t0 = __ldcs(yv + sa.x + q);
            ulonglong2 t1 = __ldcs(yv + sa.y + q);
            ulonglong2 t2 = __ldcs(yv + sa.z + q);
            ulonglong2 t3 = __ldcs(yv + sa.w + q);
            ulonglong2 t4 = __ldcs(yv + sb.x + q);
            ulonglong2 t5 = __ldcs(yv + sb.y + q);
            ulonglong2 t6 = __ldcs(yv + sb.z + q);
            ulonglong2 t7 = __ldcs(yv + sb.w + q);
            acc_lo = fadd2(acc_lo, t0.x); acc_hi = fadd2(acc_hi, t0.y);
            acc_lo = fadd2(acc_lo, t1.x); acc_hi = fadd2(acc_hi, t1.y);
            acc_lo = fadd2(acc_lo, t2.x); acc_hi = fadd2(acc_hi, t2.y);
            acc_lo = fadd2(acc_lo, t3.x); acc_hi = fadd2(acc_hi, t3.y);
            acc_lo = fadd2(acc_lo, t4.x); acc_hi = fadd2(acc_hi, t4.y);
            acc_lo = fadd2(acc_lo, t5.x); acc_hi = fadd2(acc_hi, t5.y);
            acc_lo = fadd2(acc_lo, t6.x); acc_hi = fadd2(acc_hi, t6.y);
            acc_lo = fadd2(acc_lo, t7.x); acc_hi = fadd2(acc_hi, t7.y);
        }
        for (; i < cnt; i++) {
            const ulonglong2 tt = __ldcs(yv + slots[i] + q);
            acc_lo = fadd2(acc_lo, tt.x);
            acc_hi = fadd2(acc_hi, tt.y);
        }
    }
    // color->vertex in-edges (y_c is 64 KB, L1-hot)
    {
        const int cnt = min(d_cnt_vc[v], CAPVC);
        const int* slots = d_slot_vc + v * CAPVC;
        const int4* slots4 = (const int4*)slots;
        const ulonglong2* yc = (const ulonglong2*)g_yc;
        int i = 0;
        for (; i + 4 <= cnt; i += 4) {
            const int4 sa = slots4[i >> 2];
            ulonglong2 t0 = __ldg(yc + sa.x + q);
            ulonglong2 t1 = __ldg(yc + sa.y + q);
            ulonglong2 t2 = __ldg(yc + sa.z + q);
            ulonglong2 t3 = __ldg(yc + sa.w + q);
            acc_lo = fadd2(acc_lo, t0.x); acc_hi = fadd2(acc_hi, t0.y);
            acc_lo = fadd2(acc_lo, t1.x); acc_hi = fadd2(acc_hi, t1.y);
            acc_lo = fadd2(acc_lo, t2.x); acc_hi = fadd2(acc_hi, t2.y);
            acc_lo = fadd2(acc_lo, t3.x); acc_hi = fadd2(acc_hi, t3.y);
        }
        for (; i < cnt; i++) {
            const ulonglong2 tt = __ldg(yc + slots[i] + q);
            acc_lo = fadd2(acc_lo, tt.x);
            acc_hi = fadd2(acc_hi, tt.y);
        }
    }

    if (q == 0) { d_cnt_vv[v] = 0; d_cnt_vc[v] = 0; }
    if (blockIdx.x == 0 && threadIdx.x == 0) d_flag = 0;

    float r0, r1, r2, r3;
    upk2(acc_lo, r0, r1); upk2(acc_hi, r2, r3);
    ((float4*)out)[v * 16 + q] = make_float4(fmaxf(r0, 0.f), fmaxf(r1, 0.f),
                                             fmaxf(r2, 0.f), fmaxf(r3, 0.f));
}

// ---------------------------------------------------------------------------
extern "C" void kernel_launch(void* const* d_in, const int* in_sizes, int n_in,
                              void* d_out, int out_size)
{
    const float* x_v  = (const float*)d_in[0];
    const float* x_c  = (const float*)d_in[1];
    const float* W1v  = (const float*)d_in[2];
    const float* b1v  = (const float*)d_in[3];
    const float* W2v  = (const float*)d_in[4];
    const float* b2v  = (const float*)d_in[5];
    const float* W1c  = (const float*)d_in[6];
    const float* b1c  = (const float*)d_in[7];
    const float* W2c  = (const float*)d_in[8];
    const float* b2c  = (const float*)d_in[9];
    const int* src_vv = (const int*)d_in[10];
    const int* dst_vv = (const int*)d_in[11];
    const int* src_vc = (const int*)d_in[12];
    const int* dst_vc = (const int*)d_in[13];
    float* out = (float*)d_out;

    cudaFuncSetAttribute(fused_kernel,
                         cudaFuncAttributeMaxDynamicSharedMemorySize, WBLOB);

    // 1. prep (block 0) + fill + HMMA MLP tiles, one launch
    fused_kernel<<<FUSED_GRID, 256, WBLOB>>>(
        x_v, x_c, W1v, b1v, W2v, b2v, W1c, b1c, W2c, b2c,
        src_vv, dst_vv, src_vc, dst_vc);

    // 2. gather + residual + relu (+ state self-clean)
    gather_kernel<<<NN / 16, 256>>>(x_v, out);
}

// round 16
// speedup vs baseline: 1.1338x; 1.1338x over previous
#include <cuda_runtime.h>
#include <cuda_bf16.h>
#include <cstdint>

#define NN  50000
#define NC  256
#define DD  64
#define HH  128
#define EVV 800000
#define EVC 400000

#define CAPVV 64
#define CAPVC 32

#define VTILES 391                 // ceil(50000/128)
#define CTILES 2
#define FUSED_GRID (VTILES + CTILES)   // 393

// ---- smem weight image (bytes). Row strides: stride/4 mod 32 == 4 ----
#define W1_STRIDE_W 36
#define W2_STRIDE_W 68
#define SM_W1H 0                   // 128 rows * 144B = 18432
#define SM_W1L 18432
#define SM_W2H 36864               // 64 rows * 272B = 17408
#define SM_W2L 54272
#define SM_B1S 71680
#define SM_B2S 72192
#define WBLOB  72448               // total smem per block

typedef unsigned long long ull;

// ---------------- scratch (device globals; zero-initialized) ----------------
__device__ float g_yv[NN * DD];
__device__ float g_yc[NC * DD];
__device__ int   d_cnt_vv[NN];
__device__ int   d_cnt_vc[NN];
__device__ int   d_slot_vv[NN * CAPVV];   // pre-scaled src offsets (src<<4)
__device__ int   d_slot_vc[NN * CAPVC];
__device__ __align__(16) unsigned char g_wblob[2][WBLOB];

// ---------------- helpers ----------------------------------------------------
__device__ __forceinline__ void bsplit(float v, unsigned short& h, unsigned short& l) {
    __nv_bfloat16 bh = __float2bfloat16(v);
    float r = v - __bfloat162float(bh);
    __nv_bfloat16 bl = __float2bfloat16(r);
    h = __bfloat16_as_ushort(bh);
    l = __bfloat16_as_ushort(bl);
}
__device__ __forceinline__ uint32_t pkbf(float hi_val, float lo_val) {
    uint32_t r;
    asm("cvt.rn.bf16x2.f32 %0, %1, %2;" : "=r"(r) : "f"(hi_val), "f"(lo_val));
    return r;
}
// split a float2 into packed bf16x2 hi word + residual lo word
__device__ __forceinline__ void split2(float2 v, uint32_t& wh, uint32_t& wl) {
    wh = pkbf(v.y, v.x);
    const float r0 = v.x - __uint_as_float(wh << 16);
    const float r1 = v.y - __uint_as_float(wh & 0xFFFF0000u);
    wl = pkbf(r1, r0);
}
__device__ __forceinline__ void mma16816(float* c, const uint32_t* a,
                                         uint32_t b0, uint32_t b1) {
    asm volatile(
        "mma.sync.aligned.m16n8k16.row.col.f32.bf16.bf16.f32 "
        "{%0,%1,%2,%3}, {%4,%5,%6,%7}, {%8,%9}, {%0,%1,%2,%3};"
        : "+f"(c[0]), "+f"(c[1]), "+f"(c[2]), "+f"(c[3])
        : "r"(a[0]), "r"(a[1]), "r"(a[2]), "r"(a[3]), "r"(b0), "r"(b1));
}
__device__ __forceinline__ ull pk2(float lo, float hi) {
    ull r; asm("mov.b64 %0, {%1, %2};" : "=l"(r) : "f"(lo), "f"(hi)); return r;
}
__device__ __forceinline__ void upk2(ull v, float& lo, float& hi) {
    asm("mov.b64 {%0, %1}, %2;" : "=f"(lo), "=f"(hi) : "l"(v));
}
__device__ __forceinline__ ull fadd2(ull a, ull b) {
    ull d; asm("add.rn.f32x2 %0, %1, %2;" : "=l"(d) : "l"(a), "l"(b)); return d;
}

// ---------------------------------------------------------------------------
// Prep: build smem-image weight blobs. COALESCED loads, scattered 2B stores.
// grid 64 x 256 = 16384 threads; thread g handles W1 elem (g) and W2 elem (g).
// ---------------------------------------------------------------------------
__global__ void __launch_bounds__(256) prep_kernel(
    const float* __restrict__ W1v, const float* __restrict__ b1v,
    const float* __restrict__ W2v, const float* __restrict__ b2v,
    const float* __restrict__ W1c, const float* __restrict__ b1c,
    const float* __restrict__ W2c, const float* __restrict__ b2c)
{
    const int g = blockIdx.x * 256 + threadIdx.x;       // 0..16383
    const int net = g >> 13;                             // 0 or 1
    const int idx = g & 8191;

    // W1 [64 k][128 n], element idx (coalesced load) -> image [n][k]
    {
        const float w = (net ? W1c : W1v)[idx];
        const int k = idx >> 7;
        const int n = idx & 127;
        unsigned short h, l;
        bsplit(w, h, l);
        unsigned short* W1h = (unsigned short*)(g_wblob[net] + SM_W1H);
        unsigned short* W1l = (unsigned short*)(g_wblob[net] + SM_W1L);
        W1h[n * (2 * W1_STRIDE_W) + k] = h;
        W1l[n * (2 * W1_STRIDE_W) + k] = l;
    }
    // W2 [128 j][64 c], element idx (coalesced load) -> image [c][j]
    {
        const float w = (net ? W2c : W2v)[idx];
        const int j = idx >> 6;
        const int c = idx & 63;
        unsigned short h, l;
        bsplit(w, h, l);
        unsigned short* W2h = (unsigned short*)(g_wblob[net] + SM_W2H);
        unsigned short* W2l = (unsigned short*)(g_wblob[net] + SM_W2L);
        W2h[c * (2 * W2_STRIDE_W) + j] = h;
        W2l[c * (2 * W2_STRIDE_W) + j] = l;
    }
    // biases
    if (g < HH)                ((float*)(g_wblob[0] + SM_B1S))[g] = b1v[g];
    else if (g < HH + DD)      ((float*)(g_wblob[0] + SM_B2S))[g - HH] = b2v[g - HH];
    else if (g < 2 * HH + DD)  ((float*)(g_wblob[1] + SM_B1S))[g - HH - DD] = b1c[g - HH - DD];
    else if (g < 2 * HH + 2 * DD)
        ((float*)(g_wblob[1] + SM_B2S))[g - 2 * HH - DD] = b2c[g - 2 * HH - DD];
}

// ---------------------------------------------------------------------------
__device__ __forceinline__ void fill_slice(
    int bid, int t,
    const int* __restrict__ src_vv, const int* __restrict__ dst_vv,
    const int* __restrict__ src_vc, const int* __restrict__ dst_vc)
{
    const int g = bid * 256 + t;
    const int stride = FUSED_GRID * 256;
    for (int i = g; i < EVV; i += stride) {
        const int d = dst_vv[i];
        const int p = atomicAdd(&d_cnt_vv[d], 1);
        if (p < CAPVV) d_slot_vv[d * CAPVV + p] = src_vv[i] << 4;
    }
    for (int i = g; i < EVC; i += stride) {
        const int d = dst_vc[i];
        const int p = atomicAdd(&d_cnt_vc[d], 1);
        if (p < CAPVC) d_slot_vc[d * CAPVC + p] = src_vc[i] << 4;
    }
}

// ---------------------------------------------------------------------------
// Fused: every block does a fill slice, then one 128-row HMMA MLP tile.
// A-fragments built in registers straight from global x (no X smem).
// 72.4 KB smem + <=128 regs -> 2 blocks/SM.
// ---------------------------------------------------------------------------
__global__ void __launch_bounds__(256, 2) fused_kernel(
    const float* __restrict__ x_v, const float* __restrict__ x_c,
    const int* __restrict__ src_vv, const int* __restrict__ dst_vv,
    const int* __restrict__ src_vc, const int* __restrict__ dst_vc)
{
    const int t = threadIdx.x;
    const int bid = blockIdx.x;

    fill_slice(bid, t, src_vv, dst_vv, src_vc, dst_vc);

    // ---------------- MLP tile ----------------
    extern __shared__ char smem[];
    const int tile = bid;
    const bool is_color = (tile < CTILES);
    const float* X  = is_color ? x_c : x_v;
    float*       Y  = is_color ? g_yc : g_yv;
    const int row0 = is_color ? tile * 128 : (tile - CTILES) * 128;
    const int nrows = is_color ? NC : NN;
    const int rem = min(128, nrows - row0);

    const int warp = t >> 5;
    const int lane = t & 31;
    const int qr = lane >> 2;
    const int qc = lane & 3;

    // coalesced copy of the pre-built weight image (L2)
    {
        const float4* src = (const float4*)g_wblob[is_color ? 1 : 0];
        float4* dst = (float4*)smem;
        for (int idx = t; idx < WBLOB / 16; idx += 256)
            dst[idx] = __ldcg(src + idx);
    }

    // A-fragments straight from global x, split in registers
    uint32_t ah[4][4], al[4][4];
    {
        const float* Xb = X + (size_t)row0 * DD;
        const int r0 = warp * 16 + qr;
        const bool ok0 = (r0 < rem), ok1 = (r0 + 8 < rem);
        const float2 z = make_float2(0.f, 0.f);
#pragma unroll
        for (int kb = 0; kb < 4; kb++) {
            const int k = kb * 16 + 2 * qc;
            float2 v00 = ok0 ? *(const float2*)(Xb + (size_t)r0 * DD + k) : z;
            float2 v10 = ok1 ? *(const float2*)(Xb + (size_t)(r0 + 8) * DD + k) : z;
            float2 v01 = ok0 ? *(const float2*)(Xb + (size_t)r0 * DD + k + 8) : z;
            float2 v11 = ok1 ? *(const float2*)(Xb + (size_t)(r0 + 8) * DD + k + 8) : z;
            split2(v00, ah[kb][0], al[kb][0]);
            split2(v10, ah[kb][1], al[kb][1]);
            split2(v01, ah[kb][2], al[kb][2]);
            split2(v11, ah[kb][3], al[kb][3]);
        }
    }
    __syncthreads();

    const uint32_t* W1h32 = (const uint32_t*)(smem + SM_W1H);
    const uint32_t* W1l32 = (const uint32_t*)(smem + SM_W1L);
    const uint32_t* W2h32 = (const uint32_t*)(smem + SM_W2H);
    const uint32_t* W2l32 = (const uint32_t*)(smem + SM_W2L);
    const float* b1s = (const float*)(smem + SM_B1S);
    const float* b2s = (const float*)(smem + SM_B2S);

    // ---- layer 1 + epilogue, in two nt-halves (register pressure cap) ----
    uint32_t a2h[16][2], a2l[16][2];
#pragma unroll
    for (int half = 0; half < 2; half++) {
        float acc[8][4];
#pragma unroll
        for (int nt = 0; nt < 8; nt++)
#pragma unroll
            for (int i = 0; i < 4; i++) acc[nt][i] = 0.0f;
#pragma unroll
        for (int kb = 0; kb < 4; kb++) {
#pragma unroll
            for (int nt2 = 0; nt2 < 8; nt2++) {
                const int nt = half * 8 + nt2;
                const int bw = (nt * 8 + qr) * W1_STRIDE_W + kb * 8 + qc;
                const uint32_t bh0 = W1h32[bw], bh1 = W1h32[bw + 4];
                const uint32_t bl0 = W1l32[bw], bl1 = W1l32[bw + 4];
                mma16816(acc[nt2], ah[kb], bh0, bh1);
                mma16816(acc[nt2], ah[kb], bl0, bl1);
                mma16816(acc[nt2], al[kb], bh0, bh1);
            }
        }
#pragma unroll
        for (int nt2 = 0; nt2 < 8; nt2++) {
            const int nt = half * 8 + nt2;
            const int cn = nt * 8 + 2 * qc;
            const float2 bb = *(const float2*)(b1s + cn);
            float2 p0, p1;
            p0.x = fmaxf(acc[nt2][0] + bb.x, 0.0f);
            p0.y = fmaxf(acc[nt2][1] + bb.y, 0.0f);
            p1.x = fmaxf(acc[nt2][2] + bb.x, 0.0f);
            p1.y = fmaxf(acc[nt2][3] + bb.y, 0.0f);
            split2(p0, a2h[nt][0], a2l[nt][0]);
            split2(p1, a2h[nt][1], a2l[nt][1]);
        }
    }

    // ---- layer 2: acc2[8][4] = H(128x128) @ W2(128x64) ----
    float acc2[8][4];
#pragma unroll
    for (int nt = 0; nt < 8; nt++)
#pragma unroll
        for (int i = 0; i < 4; i++) acc2[nt][i] = 0.0f;

#pragma unroll
    for (int kb = 0; kb < 8; kb++) {
        uint32_t fh[4], fl[4];
        fh[0] = a2h[2 * kb][0];     fh[1] = a2h[2 * kb][1];
        fh[2] = a2h[2 * kb + 1][0]; fh[3] = a2h[2 * kb + 1][1];
        fl[0] = a2l[2 * kb][0];     fl[1] = a2l[2 * kb][1];
        fl[2] = a2l[2 * kb + 1][0]; fl[3] = a2l[2 * kb + 1][1];
#pragma unroll
        for (int nt = 0; nt < 8; nt++) {
            const int bw = (nt * 8 + qr) * W2_STRIDE_W + kb * 8 + qc;
            const uint32_t bh0 = W2h32[bw], bh1 = W2h32[bw + 4];
            const uint32_t bl0 = W2l32[bw], bl1 = W2l32[bw + 4];
            mma16816(acc2[nt], fh, bh0, bh1);
            mma16816(acc2[nt], fh, bl0, bl1);
            mma16816(acc2[nt], fl, bh0, bh1);
        }
    }

    // ---- epilogue 2: y = acc2 + b2 -> global ----
    {
        const int rl0 = warp * 16 + qr;
#pragma unroll
        for (int nt = 0; nt < 8; nt++) {
            const int c = nt * 8 + 2 * qc;
            const float2 bb = *(const float2*)(b2s + c);
            if (rl0 < rem) {
                float2 y; y.x = acc2[nt][0] + bb.x; y.y = acc2[nt][1] + bb.y;
                *(float2*)(Y + (size_t)(row0 + rl0) * DD + c) = y;
            }
            if (rl0 + 8 < rem) {
                float2 y; y.x = acc2[nt][2] + bb.x; y.y = acc2[nt][3] + bb.y;
                *(float2*)(Y + (size_t)(row0 + rl0 + 8) * DD + c) = y;
            }
        }
    }
}

// ---------------------------------------------------------------------------
// Gather: 2 vertices per warp, lane = float4 chunk; pre-scaled int4 slots.
// ---------------------------------------------------------------------------
__global__ void __launch_bounds__(256) gather_kernel(
    const float* __restrict__ x_v, float* __restrict__ out)
{
    const int gwarp = (blockIdx.x * 256 + threadIdx.x) >> 5;
    const int lane = threadIdx.x & 31;
    const int half = lane >> 4;
    const int q = lane & 15;
    const int v = gwarp * 2 + half;

    float4 a4 = ((const float4*)x_v)[v * 16 + q];
    ull acc_lo = pk2(a4.x, a4.y);
    ull acc_hi = pk2(a4.z, a4.w);

    // vertex->vertex in-edges (y_v L2-resident)
    {
        const int cnt = min(d_cnt_vv[v], CAPVV);
        const int* slots = d_slot_vv + v * CAPVV;
        const int4* slots4 = (const int4*)slots;
        const ulonglong2* yv = (const ulonglong2*)g_yv;
        int i = 0;
        for (; i + 8 <= cnt; i += 8) {
            const int4 sa = slots4[i >> 2];
            const int4 sb = slots4[(i >> 2) + 1];
            ulonglong2 t0 = __ldcs(yv + sa.x + q);
            ulonglong2 t1 = __ldcs(yv + sa.y + q);
            ulonglong2 t2 = __ldcs(yv + sa.z + q);
            ulonglong2 t3 = __ldcs(yv + sa.w + q);
            ulonglong2 t4 = __ldcs(yv + sb.x + q);
            ulonglong2 t5 = __ldcs(yv + sb.y + q);
            ulonglong2 t6 = __ldcs(yv + sb.z + q);
            ulonglong2 t7 = __ldcs(yv + sb.w + q);
            acc_lo = fadd2(acc_lo, t0.x); acc_hi = fadd2(acc_hi, t0.y);
            acc_lo = fadd2(acc_lo, t1.x); acc_hi = fadd2(acc_hi, t1.y);
            acc_lo = fadd2(acc_lo, t2.x); acc_hi = fadd2(acc_hi, t2.y);
            acc_lo = fadd2(acc_lo, t3.x); acc_hi = fadd2(acc_hi, t3.y);
            acc_lo = fadd2(acc_lo, t4.x); acc_hi = fadd2(acc_hi, t4.y);
            acc_lo = fadd2(acc_lo, t5.x); acc_hi = fadd2(acc_hi, t5.y);
            acc_lo = fadd2(acc_lo, t6.x); acc_hi = fadd2(acc_hi, t6.y);
            acc_lo = fadd2(acc_lo, t7.x); acc_hi = fadd2(acc_hi, t7.y);
        }
        for (; i < cnt; i++) {
            const ulonglong2 tt = __ldcs(yv + slots[i] + q);
            acc_lo = fadd2(acc_lo, tt.x);
            acc_hi = fadd2(acc_hi, tt.y);
        }
    }
    // color->vertex in-edges (y_c is 64 KB, L1-hot)
    {
        const int cnt = min(d_cnt_vc[v], CAPVC);
        const int* slots = d_slot_vc + v * CAPVC;
        const int4* slots4 = (const int4*)slots;
        const ulonglong2* yc = (const ulonglong2*)g_yc;
        int i = 0;
        for (; i + 4 <= cnt; i += 4) {
            const int4 sa = slots4[i >> 2];
            ulonglong2 t0 = __ldg(yc + sa.x + q);
            ulonglong2 t1 = __ldg(yc + sa.y + q);
            ulonglong2 t2 = __ldg(yc + sa.z + q);
            ulonglong2 t3 = __ldg(yc + sa.w + q);
            acc_lo = fadd2(acc_lo, t0.x); acc_hi = fadd2(acc_hi, t0.y);
            acc_lo = fadd2(acc_lo, t1.x); acc_hi = fadd2(acc_hi, t1.y);
            acc_lo = fadd2(acc_lo, t2.x); acc_hi = fadd2(acc_hi, t2.y);
            acc_lo = fadd2(acc_lo, t3.x); acc_hi = fadd2(acc_hi, t3.y);
        }
        for (; i < cnt; i++) {
            const ulonglong2 tt = __ldg(yc + slots[i] + q);
            acc_lo = fadd2(acc_lo, tt.x);
            acc_hi = fadd2(acc_hi, tt.y);
        }
    }

    if (q == 0) { d_cnt_vv[v] = 0; d_cnt_vc[v] = 0; }

    float r0, r1, r2, r3;
    upk2(acc_lo, r0, r1); upk2(acc_hi, r2, r3);
    ((float4*)out)[v * 16 + q] = make_float4(fmaxf(r0, 0.f), fmaxf(r1, 0.f),
                                             fmaxf(r2, 0.f), fmaxf(r3, 0.f));
}

// ---------------------------------------------------------------------------
extern "C" void kernel_launch(void* const* d_in, const int* in_sizes, int n_in,
                              void* d_out, int out_size)
{
    const float* x_v  = (const float*)d_in[0];
    const float* x_c  = (const float*)d_in[1];
    const float* W1v  = (const float*)d_in[2];
    const float* b1v  = (const float*)d_in[3];
    const float* W2v  = (const float*)d_in[4];
    const float* b2v  = (const float*)d_in[5];
    const float* W1c  = (const float*)d_in[6];
    const float* b1c  = (const float*)d_in[7];
    const float* W2c  = (const float*)d_in[8];
    const float* b2c  = (const float*)d_in[9];
    const int* src_vv = (const int*)d_in[10];
    const int* dst_vv = (const int*)d_in[11];
    const int* src_vc = (const int*)d_in[12];
    const int* dst_vc = (const int*)d_in[13];
    float* out = (float*)d_out;

    cudaFuncSetAttribute(fused_kernel,
                         cudaFuncAttributeMaxDynamicSharedMemorySize, WBLOB);

    // 1. build smem-image weight blobs (coalesced loads, scattered stores)
    prep_kernel<<<64, 256>>>(W1v, b1v, W2v, b2v, W1c, b1c, W2c, b2c);
    // 2. fill slice + HMMA MLP tile per block (2 blocks/SM)
    fused_kernel<<<FUSED_GRID, 256, WBLOB>>>(
        x_v, x_c, src_vv, dst_vv, src_vc, dst_vc);
    // 3. gather + residual + relu (+ counter self-clean)
    gather_kernel<<<NN / 16, 256>>>(x_v, out);
}